// round 13
// baseline (speedup 1.0000x reference)
#include <cuda_runtime.h>
#include <cuda_bf16.h>
#include <stdint.h>

#define QN 32
#define DN 4096
#define DIMN 384
#define N2 192
#define QD (QN*DN)
#define AW 100            // k1 doc smem row stride in words
#define BW1 196           // W smem row stride in words (384 bf16 = 192 w + 4 pad)
#define AW2 52            // k2 h1 chunk stride: 48 words (96 bf16) + 4 pad

static __device__ __align__(16) float         g_A32[QN*DIMN];
static __device__ __align__(16) float         g_dense[QD];
static __device__ __align__(16) __nv_bfloat16 g_Bd[DN*DIMN];
static __device__ __align__(16) __nv_bfloat16 g_W2T[N2*DIMN];     // [n][k] bf16
static __device__ __align__(16) __nv_bfloat16 g_W1dT[DIMN*DIMN];  // [n][k] bf16

__device__ __forceinline__ void mma16816(float* c, const uint32_t* a, const uint32_t* b){
    asm volatile(
        "mma.sync.aligned.m16n8k16.row.col.f32.bf16.bf16.f32 "
        "{%0,%1,%2,%3}, {%4,%5,%6,%7}, {%8,%9}, {%0,%1,%2,%3};"
        : "+f"(c[0]), "+f"(c[1]), "+f"(c[2]), "+f"(c[3])
        : "r"(a[0]), "r"(a[1]), "r"(a[2]), "r"(a[3]), "r"(b[0]), "r"(b[1]));
}
__device__ __forceinline__ void ldsm4(uint32_t* r, uint32_t addr){
    asm volatile("ldmatrix.sync.aligned.m8n8.x4.shared.b16 {%0,%1,%2,%3}, [%4];"
        : "=r"(r[0]), "=r"(r[1]), "=r"(r[2]), "=r"(r[3]) : "r"(addr));
}
__device__ __forceinline__ uint32_t smem_u32(const void* p){
    uint32_t a;
    asm("{ .reg .u64 t; cvta.to.shared.u64 t, %1; cvt.u32.u64 %0, t; }" : "=r"(a) : "l"(p));
    return a;
}
__device__ __forceinline__ uint32_t packbf(float x, float y){
    __nv_bfloat162 h = __floats2bfloat162_rn(x, y);
    return *(uint32_t*)&h;
}

// ---- launch 1: transposes only (W2 -> W2T, W1d -> W1dT) ------------------
#define TBLK_W2 72
#define TBLK_W1 144
__global__ __launch_bounds__(256) void hr_prep_t(
    const float* __restrict__ W1, const float* __restrict__ W2)
{
    __shared__ float ts[32][33];
    int blk = blockIdx.x, tid = threadIdx.x;
    int tx = tid & 31, ty = tid >> 5;
    const float* src; __nv_bfloat16* dst;
    int kt, nt, src_ld, dst_ld;
    if (blk < TBLK_W2) { kt = blk / 6;  nt = blk - kt * 6;
        src = W2;  dst = g_W2T;  src_ld = N2;  dst_ld = DIMN; }
    else { int b = blk - TBLK_W2; kt = b / 12; nt = b - kt * 12;
        src = W1 + DIMN * DIMN;  dst = g_W1dT;  src_ld = DIMN;  dst_ld = DIMN; }
#pragma unroll
    for (int j = 0; j < 4; j++) {
        int k = kt * 32 + ty + 8 * j;
        ts[ty + 8 * j][tx] = src[(size_t)k * src_ld + nt * 32 + tx];
    }
    __syncthreads();
#pragma unroll
    for (int j = 0; j < 4; j++) {
        int n = nt * 32 + ty + 8 * j;
        dst[(size_t)n * dst_ld + kt * 32 + tx] = __float2bfloat16(ts[tx][ty + 8 * j]);
    }
}

// ---- launch 2: fused K1 | A32 | dense ------------------------------------
#define K1BLK 256
#define ABLK 384
#define DBLK 128
__global__ __launch_bounds__(256, 2) void hr_k1f(
    const float* __restrict__ doc, const float* __restrict__ qd,
    const float* __restrict__ W1, const float* __restrict__ b1)
{
    extern __shared__ uint32_t smw[];
    const int tid = threadIdx.x, lane = tid & 31, wid = tid >> 5;
    int blk = blockIdx.x;

    if (blk >= K1BLK) {
        blk -= K1BLK;
        float* shm = (float*)smw;
        if (blk < ABLK) {                  // A32, 8-way k-split
            int q = blk / 12, nc = blk - q * 12;
            float* qds = shm;
            float* part = shm + DIMN;
            for (int i = tid; i < DIMN; i += 256) qds[i] = qd[q * DIMN + i];
            __syncthreads();
            int n = nc * 32 + lane;
            float s = 0.f;
#pragma unroll
            for (int i = 0; i < 48; i++) {
                int k = wid * 48 + i;
                s = fmaf(W1[(size_t)k * DIMN + n], qds[k], s);
            }
            part[wid * 32 + lane] = s;
            __syncthreads();
            if (tid < 32) {
                int nn = nc * 32 + tid;
                float acc = b1[nn];
#pragma unroll
                for (int w2 = 0; w2 < 8; w2++) acc += part[w2 * 32 + tid];
                g_A32[q * DIMN + nn] = acc;
            }
            return;
        }
        {                                  // dense = query @ doc^T, 4 docs/warp
            int db = blk - ABLK;
            for (int i = tid; i < QN * DIMN; i += 256) shm[i] = qd[i];
            __syncthreads();
            int d0 = db * 32 + wid * 4;
            float dr[4][12];
#pragma unroll
            for (int j = 0; j < 4; j++)
#pragma unroll
                for (int i = 0; i < 12; i++)
                    dr[j][i] = doc[(size_t)(d0 + j) * DIMN + lane + 32 * i];
            for (int qi = 0; qi < QN; qi++) {
                float s0 = 0.f, s1 = 0.f, s2 = 0.f, s3 = 0.f;
#pragma unroll
                for (int i = 0; i < 12; i++) {
                    float qv = shm[qi * DIMN + lane + 32 * i];
                    s0 = fmaf(dr[0][i], qv, s0);
                    s1 = fmaf(dr[1][i], qv, s1);
                    s2 = fmaf(dr[2][i], qv, s2);
                    s3 = fmaf(dr[3][i], qv, s3);
                }
#pragma unroll
                for (int o = 16; o; o >>= 1) {
                    s0 += __shfl_xor_sync(0xffffffffu, s0, o);
                    s1 += __shfl_xor_sync(0xffffffffu, s1, o);
                    s2 += __shfl_xor_sync(0xffffffffu, s2, o);
                    s3 += __shfl_xor_sync(0xffffffffu, s3, o);
                }
                if (lane == 0) {
                    g_dense[qi * DN + d0]     = s0;
                    g_dense[qi * DN + d0 + 1] = s1;
                    g_dense[qi * DN + d0 + 2] = s2;
                    g_dense[qi * DN + d0 + 3] = s3;
                }
            }
            return;
        }
    }

    // ---- K1 role: Bd = doc @ W1d, 64x96 tiles ----
    uint32_t* Wsm = smw;
    uint32_t* Asm = smw + 96 * BW1;
    const int wm = wid & 1, wn = wid >> 1;
    const int d0 = (blk >> 2) * 64, n0 = (blk & 3) * 96;

    for (int i = tid; i < 96 * 192; i += 256) {
        int n = i / 192, w = i - n * 192;
        Wsm[n * BW1 + w] = ((const uint32_t*)g_W1dT)[(size_t)(n0 + n) * 192 + w];
    }
    float acc[2][3][4];
#pragma unroll
    for (int a = 0; a < 2; a++)
#pragma unroll
        for (int b = 0; b < 3; b++)
#pragma unroll
            for (int c = 0; c < 4; c++) acc[a][b][c] = 0.f;

    for (int ch = 0; ch < 2; ch++) {
        __syncthreads();
        for (int i = tid; i < 64 * 96; i += 256) {
            int r = i / 96, c = i - r * 96;
            float2 dv = *(const float2*)&doc[(size_t)(d0 + r) * DIMN + ch * 192 + 2 * c];
            Asm[r * AW + c] = packbf(dv.x, dv.y);
        }
        __syncthreads();
#pragma unroll
        for (int ks = 0; ks < 12; ks++) {
            uint32_t a[2][4], bf[3][2];
#pragma unroll
            for (int im = 0; im < 2; im++) {
                const uint32_t* p = Asm + (wm * 32 + im * 16 + (lane >> 2)) * AW + ks * 8 + (lane & 3);
                a[im][0] = p[0]; a[im][1] = p[8 * AW]; a[im][2] = p[4]; a[im][3] = p[8 * AW + 4];
            }
#pragma unroll
            for (int jn = 0; jn < 3; jn++) {
                const uint32_t* p = Wsm + (wn * 24 + jn * 8 + (lane >> 2)) * BW1 + ch * 96 + ks * 8 + (lane & 3);
                bf[jn][0] = p[0]; bf[jn][1] = p[4];
            }
#pragma unroll
            for (int im = 0; im < 2; im++)
#pragma unroll
                for (int jn = 0; jn < 3; jn++) mma16816(acc[im][jn], a[im], bf[jn]);
        }
    }
#pragma unroll
    for (int im = 0; im < 2; im++)
#pragma unroll
        for (int hf = 0; hf < 2; hf++) {
            int d = d0 + wm * 32 + im * 16 + hf * 8 + (lane >> 2);
#pragma unroll
            for (int jn = 0; jn < 3; jn++) {
                int n = n0 + wn * 24 + jn * 8 + (lane & 3) * 2;
                ((uint32_t*)g_Bd)[(size_t)d * 192 + (n >> 1)] =
                    packbf(acc[im][jn][hf * 2], acc[im][jn][hf * 2 + 1]);
            }
        }
}

// ---- K2: double-buffered h1 + ldmatrix + HMMA, 512 threads, persistent ---
__global__ __launch_bounds__(512, 1) void hr_k2(
    const float* __restrict__ sparse, const float* __restrict__ W1,
    const float* __restrict__ b2, const float* __restrict__ W3,
    const float* __restrict__ b3, float* __restrict__ out, int out_size)
{
    extern __shared__ uint32_t smw[];
    uint32_t* Wsm  = smw;                          // [192][BW1]
    uint32_t* Abuf0 = smw + N2 * BW1;              // [128][AW2]
    uint32_t* Abuf1 = Abuf0 + 128 * AW2;           // [128][AW2]
    float* b2s = (float*)(Abuf1 + 128 * AW2);
    float* w3s = b2s + N2;
    float* a_s = w3s + N2;
    float* u_s = a_s + DIMN;
    float* v_s = u_s + DIMN;
    float* dns = v_s + DIMN;
    float* sps = dns + 128;
    float* zbuf = sps + 128;
    const int tid = threadIdx.x, lane = tid & 31, wid = tid >> 5;
    const int wm = wid & 3, wn = wid >> 2;   // 4 x 4 warp grid, tile 32m x 48n
    uint32_t* Abufs[2] = {Abuf0, Abuf1};

    // ldmatrix lane-address components (bytes)
    const uint32_t wsm_b  = smem_u32(Wsm);
    const uint32_t abuf_b[2] = {smem_u32(Abuf0), smem_u32(Abuf1)};
    const uint32_t a_lane_off =
        ((uint32_t)((wm * 32 + (lane & 7) + (lane & 8)) * AW2 + ((lane & 16) ? 4 : 0))) * 4u;
    const uint32_t b_lane_off =
        ((uint32_t)((wn * 48 + (lane & 7) + ((lane & 16) >> 1)) * BW1 + ((lane & 8) ? 4 : 0))) * 4u;

    for (int i = tid; i < N2 * 48; i += 512) {
        int n = i / 48, w4 = i - n * 48;
        *(uint4*)&Wsm[n * BW1 + w4 * 4] = ((const uint4*)g_W2T)[(size_t)n * 48 + w4];
    }
    for (int i = tid; i < N2; i += 512) { b2s[i] = b2[i]; w3s[i] = W3[i]; }
    for (int i = tid; i < DIMN; i += 512) {
        u_s[i] = W1[768 * DIMN + i];
        v_s[i] = W1[769 * DIMN + i];
    }

    for (int u = blockIdx.x; u < QN * 32; u += gridDim.x) {
        int q = u >> 5, dt = u & 31, d0 = dt << 7;
        __syncthreads();                               // prev unit done with smem
        for (int i = tid; i < DIMN; i += 512) a_s[i] = g_A32[q * DIMN + i];
        if (tid < 128) {
            dns[tid] = g_dense[q * DN + d0 + tid];
            sps[tid] = sparse[q * DN + d0 + tid];
            zbuf[tid] = 0.f;
        }
        __syncthreads();                               // a_s/dns/sps ready

        float acc[2][6][4];
#pragma unroll
        for (int a = 0; a < 2; a++)
#pragma unroll
            for (int b = 0; b < 6; b++)
#pragma unroll
                for (int c = 0; c < 4; c++) acc[a][b][c] = 0.f;

        // build chunk 0
        {
            uint32_t* A = Abufs[0];
#pragma unroll 2
            for (int i = tid; i < 128 * 48; i += 512) {
                int r = i / 48, c = i - r * 48;
                int k = 2 * c;
                float dsc = dns[r], ssc = sps[r];
                uint32_t bdw = ((const uint32_t*)g_Bd)[(size_t)(d0 + r) * 192 + c];
                float2 bv = __bfloat1622float2(*(__nv_bfloat162*)&bdw);
                float2 av = *(const float2*)&a_s[k];
                float2 uv = *(const float2*)&u_s[k];
                float2 vv = *(const float2*)&v_s[k];
                float x0 = av.x + bv.x + dsc * uv.x + ssc * vv.x;
                float x1 = av.y + bv.y + dsc * uv.y + ssc * vv.y;
                A[r * AW2 + c] = packbf(fmaxf(x0, 0.f), fmaxf(x1, 0.f));
            }
        }
        __syncthreads();

#pragma unroll 1
        for (int ch = 0; ch < 4; ch++) {
            if (ch < 3) {                              // build next chunk, other buffer
                uint32_t* A = Abufs[(ch + 1) & 1];
                int kb = (ch + 1) * 48;
#pragma unroll 2
                for (int i = tid; i < 128 * 48; i += 512) {
                    int r = i / 48, c = i - r * 48;
                    int k = 2 * (kb + c);
                    float dsc = dns[r], ssc = sps[r];
                    uint32_t bdw = ((const uint32_t*)g_Bd)[(size_t)(d0 + r) * 192 + kb + c];
                    float2 bv = __bfloat1622float2(*(__nv_bfloat162*)&bdw);
                    float2 av = *(const float2*)&a_s[k];
                    float2 uv = *(const float2*)&u_s[k];
                    float2 vv = *(const float2*)&v_s[k];
                    float x0 = av.x + bv.x + dsc * uv.x + ssc * vv.x;
                    float x1 = av.y + bv.y + dsc * uv.y + ssc * vv.y;
                    A[r * AW2 + c] = packbf(fmaxf(x0, 0.f), fmaxf(x1, 0.f));
                }
            }
            // mma on current chunk via ldmatrix
            {
                uint32_t abase = abuf_b[ch & 1] + a_lane_off;
                uint32_t bbase = wsm_b + b_lane_off + (uint32_t)(ch * 48) * 4u;
#pragma unroll
                for (int ks = 0; ks < 6; ks++) {
                    uint32_t a[2][4], bfr[3][4];
#pragma unroll
                    for (int im = 0; im < 2; im++)
                        ldsm4(a[im], abase + (uint32_t)(im * 16 * AW2 * 4 + ks * 32));
#pragma unroll
                    for (int p = 0; p < 3; p++)
                        ldsm4(bfr[p], bbase + (uint32_t)(p * 16 * BW1 * 4 + ks * 32));
#pragma unroll
                    for (int im = 0; im < 2; im++)
#pragma unroll
                        for (int p = 0; p < 3; p++) {
                            mma16816(acc[im][2 * p],     a[im], &bfr[p][0]);
                            mma16816(acc[im][2 * p + 1], a[im], &bfr[p][2]);
                        }
                }
            }
            __syncthreads();
        }

        // epilogue: z[m] = sum_n relu(D + b2) * W3
#pragma unroll
        for (int im = 0; im < 2; im++)
#pragma unroll
            for (int hf = 0; hf < 2; hf++) {
                int m = wm * 32 + im * 16 + hf * 8 + (lane >> 2);
                float val = 0.f;
#pragma unroll
                for (int jn = 0; jn < 6; jn++) {
                    int n = wn * 48 + jn * 8 + (lane & 3) * 2;
                    val += fmaxf(acc[im][jn][hf * 2]     + b2s[n],     0.f) * w3s[n];
                    val += fmaxf(acc[im][jn][hf * 2 + 1] + b2s[n + 1], 0.f) * w3s[n + 1];
                }
                val += __shfl_xor_sync(0xffffffffu, val, 1);
                val += __shfl_xor_sync(0xffffffffu, val, 2);
                if ((lane & 3) == 0) atomicAdd(&zbuf[m], val);
            }
        __syncthreads();
        if (tid < 128) {
            float z = zbuf[tid] + b3[0];
            float w = 1.f / (1.f + expf(-z));
            float dn = dns[tid], sp = sps[tid];
            float fin = w * dn + (1.f - w) * sp;
            int o = q * DN + d0 + tid;
            if (o < out_size)          out[o] = fin;
            if (QD + o < out_size)     out[QD + o] = dn;
            if (2 * QD + o < out_size) out[2 * QD + o] = sp;
        }
    }
}

extern "C" void kernel_launch(void* const* d_in, const int* in_sizes, int n_in,
                              void* d_out, int out_size)
{
    const float* qd     = (const float*)d_in[0];
    const float* doc    = (const float*)d_in[1];
    const float* sparse = (const float*)d_in[2];
    const float* W1     = (const float*)d_in[3];
    const float* b1     = (const float*)d_in[4];
    const float* W2     = (const float*)d_in[5];
    const float* b2     = (const float*)d_in[6];
    const float* W3     = (const float*)d_in[7];
    const float* b3     = (const float*)d_in[8];
    float* out = (float*)d_out;

    const int SMEM_K1 = (96 * BW1 + 64 * AW) * 4;                         // 100864
    const int SMEM_K2 = (N2 * BW1 + 2 * 128 * AW2 + 1920) * 4;            // 211456
    cudaFuncSetAttribute(hr_k1f, cudaFuncAttributeMaxDynamicSharedMemorySize, SMEM_K1);
    cudaFuncSetAttribute(hr_k2, cudaFuncAttributeMaxDynamicSharedMemorySize, SMEM_K2);

    hr_prep_t<<<TBLK_W2 + TBLK_W1, 256>>>(W1, W2);
    hr_k1f<<<K1BLK + ABLK + DBLK, 256, SMEM_K1>>>(doc, qd, W1, b1);
    hr_k2<<<148, 512, SMEM_K2>>>(sparse, W1, b2, W3, b3, out, out_size);
}

// round 16
// speedup vs baseline: 1.3836x; 1.3836x over previous
#include <cuda_runtime.h>
#include <cuda_bf16.h>
#include <stdint.h>

#define QN 32
#define DN 4096
#define DIMN 384
#define N2 192
#define QD (QN*DN)
#define AW 100            // h1/doc smem row stride in words (192 bf16 = 96 w + 4 pad)
#define BW1 196           // W smem row stride in words (384 bf16 = 192 w + 4 pad)

static __device__ __align__(16) float         g_A32[QN*DIMN];
static __device__ __align__(16) float         g_dense[QD];
static __device__ __align__(16) __nv_bfloat16 g_Bd[DN*DIMN];
static __device__ __align__(16) __nv_bfloat16 g_W2T[N2*DIMN];     // [n][k] bf16
static __device__ __align__(16) __nv_bfloat16 g_W1dT[DIMN*DIMN];  // [n][k] bf16

__device__ __forceinline__ void mma16816(float* c, const uint32_t* a, const uint32_t* b){
    asm volatile(
        "mma.sync.aligned.m16n8k16.row.col.f32.bf16.bf16.f32 "
        "{%0,%1,%2,%3}, {%4,%5,%6,%7}, {%8,%9}, {%0,%1,%2,%3};"
        : "+f"(c[0]), "+f"(c[1]), "+f"(c[2]), "+f"(c[3])
        : "r"(a[0]), "r"(a[1]), "r"(a[2]), "r"(a[3]), "r"(b[0]), "r"(b[1]));
}
__device__ __forceinline__ void ldsm4(uint32_t* r, uint32_t addr){
    asm volatile("ldmatrix.sync.aligned.m8n8.x4.shared.b16 {%0,%1,%2,%3}, [%4];"
        : "=r"(r[0]), "=r"(r[1]), "=r"(r[2]), "=r"(r[3]) : "r"(addr));
}
__device__ __forceinline__ uint32_t smem_u32(const void* p){
    uint32_t a;
    asm("{ .reg .u64 t; cvta.to.shared.u64 t, %1; cvt.u32.u64 %0, t; }" : "=r"(a) : "l"(p));
    return a;
}
__device__ __forceinline__ uint32_t packbf(float x, float y){
    __nv_bfloat162 h = __floats2bfloat162_rn(x, y);
    return *(uint32_t*)&h;
}

// ---- launch 1: transposes only (W2 -> W2T, W1d -> W1dT) ------------------
#define TBLK_W2 72
#define TBLK_W1 144
__global__ __launch_bounds__(256) void hr_prep_t(
    const float* __restrict__ W1, const float* __restrict__ W2)
{
    __shared__ float ts[32][33];
    int blk = blockIdx.x, tid = threadIdx.x;
    int tx = tid & 31, ty = tid >> 5;
    const float* src; __nv_bfloat16* dst;
    int kt, nt, src_ld, dst_ld;
    if (blk < TBLK_W2) { kt = blk / 6;  nt = blk - kt * 6;
        src = W2;  dst = g_W2T;  src_ld = N2;  dst_ld = DIMN; }
    else { int b = blk - TBLK_W2; kt = b / 12; nt = b - kt * 12;
        src = W1 + DIMN * DIMN;  dst = g_W1dT;  src_ld = DIMN;  dst_ld = DIMN; }
#pragma unroll
    for (int j = 0; j < 4; j++) {
        int k = kt * 32 + ty + 8 * j;
        ts[ty + 8 * j][tx] = src[(size_t)k * src_ld + nt * 32 + tx];
    }
    __syncthreads();
#pragma unroll
    for (int j = 0; j < 4; j++) {
        int n = nt * 32 + ty + 8 * j;
        dst[(size_t)n * dst_ld + kt * 32 + tx] = __float2bfloat16(ts[tx][ty + 8 * j]);
    }
}

// ---- launch 2: fused K1 | A32 | dense ------------------------------------
#define K1BLK 256
#define ABLK 384
#define DBLK 128
__global__ __launch_bounds__(256, 2) void hr_k1f(
    const float* __restrict__ doc, const float* __restrict__ qd,
    const float* __restrict__ W1, const float* __restrict__ b1)
{
    extern __shared__ uint32_t smw[];
    const int tid = threadIdx.x, lane = tid & 31, wid = tid >> 5;
    int blk = blockIdx.x;

    if (blk >= K1BLK) {
        blk -= K1BLK;
        float* shm = (float*)smw;
        if (blk < ABLK) {                  // A32, 8-way k-split
            int q = blk / 12, nc = blk - q * 12;
            float* qds = shm;
            float* part = shm + DIMN;
            for (int i = tid; i < DIMN; i += 256) qds[i] = qd[q * DIMN + i];
            __syncthreads();
            int n = nc * 32 + lane;
            float s = 0.f;
#pragma unroll
            for (int i = 0; i < 48; i++) {
                int k = wid * 48 + i;
                s = fmaf(W1[(size_t)k * DIMN + n], qds[k], s);
            }
            part[wid * 32 + lane] = s;
            __syncthreads();
            if (tid < 32) {
                int nn = nc * 32 + tid;
                float acc = b1[nn];
#pragma unroll
                for (int w2 = 0; w2 < 8; w2++) acc += part[w2 * 32 + tid];
                g_A32[q * DIMN + nn] = acc;
            }
            return;
        }
        {                                  // dense = query @ doc^T, 4 docs/warp
            int db = blk - ABLK;
            for (int i = tid; i < QN * DIMN; i += 256) shm[i] = qd[i];
            __syncthreads();
            int d0 = db * 32 + wid * 4;
            float dr[4][12];
#pragma unroll
            for (int j = 0; j < 4; j++)
#pragma unroll
                for (int i = 0; i < 12; i++)
                    dr[j][i] = doc[(size_t)(d0 + j) * DIMN + lane + 32 * i];
            for (int qi = 0; qi < QN; qi++) {
                float s0 = 0.f, s1 = 0.f, s2 = 0.f, s3 = 0.f;
#pragma unroll
                for (int i = 0; i < 12; i++) {
                    float qv = shm[qi * DIMN + lane + 32 * i];
                    s0 = fmaf(dr[0][i], qv, s0);
                    s1 = fmaf(dr[1][i], qv, s1);
                    s2 = fmaf(dr[2][i], qv, s2);
                    s3 = fmaf(dr[3][i], qv, s3);
                }
#pragma unroll
                for (int o = 16; o; o >>= 1) {
                    s0 += __shfl_xor_sync(0xffffffffu, s0, o);
                    s1 += __shfl_xor_sync(0xffffffffu, s1, o);
                    s2 += __shfl_xor_sync(0xffffffffu, s2, o);
                    s3 += __shfl_xor_sync(0xffffffffu, s3, o);
                }
                if (lane == 0) {
                    g_dense[qi * DN + d0]     = s0;
                    g_dense[qi * DN + d0 + 1] = s1;
                    g_dense[qi * DN + d0 + 2] = s2;
                    g_dense[qi * DN + d0 + 3] = s3;
                }
            }
            return;
        }
    }

    // ---- K1 role: Bd = doc @ W1d, 64x96 tiles ----
    uint32_t* Wsm = smw;
    uint32_t* Asm = smw + 96 * BW1;
    const int wm = wid & 1, wn = wid >> 1;
    const int d0 = (blk >> 2) * 64, n0 = (blk & 3) * 96;

    for (int i = tid; i < 96 * 192; i += 256) {
        int n = i / 192, w = i - n * 192;
        Wsm[n * BW1 + w] = ((const uint32_t*)g_W1dT)[(size_t)(n0 + n) * 192 + w];
    }
    float acc[2][3][4];
#pragma unroll
    for (int a = 0; a < 2; a++)
#pragma unroll
        for (int b = 0; b < 3; b++)
#pragma unroll
            for (int c = 0; c < 4; c++) acc[a][b][c] = 0.f;

    for (int ch = 0; ch < 2; ch++) {
        __syncthreads();
        for (int i = tid; i < 64 * 96; i += 256) {
            int r = i / 96, c = i - r * 96;
            float2 dv = *(const float2*)&doc[(size_t)(d0 + r) * DIMN + ch * 192 + 2 * c];
            Asm[r * AW + c] = packbf(dv.x, dv.y);
        }
        __syncthreads();
#pragma unroll
        for (int ks = 0; ks < 12; ks++) {
            uint32_t a[2][4], bf[3][2];
#pragma unroll
            for (int im = 0; im < 2; im++) {
                const uint32_t* p = Asm + (wm * 32 + im * 16 + (lane >> 2)) * AW + ks * 8 + (lane & 3);
                a[im][0] = p[0]; a[im][1] = p[8 * AW]; a[im][2] = p[4]; a[im][3] = p[8 * AW + 4];
            }
#pragma unroll
            for (int jn = 0; jn < 3; jn++) {
                const uint32_t* p = Wsm + (wn * 24 + jn * 8 + (lane >> 2)) * BW1 + ch * 96 + ks * 8 + (lane & 3);
                bf[jn][0] = p[0]; bf[jn][1] = p[4];
            }
#pragma unroll
            for (int im = 0; im < 2; im++)
#pragma unroll
                for (int jn = 0; jn < 3; jn++) mma16816(acc[im][jn], a[im], bf[jn]);
        }
    }
#pragma unroll
    for (int im = 0; im < 2; im++)
#pragma unroll
        for (int hf = 0; hf < 2; hf++) {
            int d = d0 + wm * 32 + im * 16 + hf * 8 + (lane >> 2);
#pragma unroll
            for (int jn = 0; jn < 3; jn++) {
                int n = n0 + wn * 24 + jn * 8 + (lane & 3) * 2;
                ((uint32_t*)g_Bd)[(size_t)d * 192 + (n >> 1)] =
                    packbf(acc[im][jn][hf * 2], acc[im][jn][hf * 2 + 1]);
            }
        }
}

// ---- K2: R11 structure + ldmatrix fragments, 512 threads, persistent -----
__global__ __launch_bounds__(512, 1) void hr_k2(
    const float* __restrict__ sparse, const float* __restrict__ W1,
    const float* __restrict__ b2, const float* __restrict__ W3,
    const float* __restrict__ b3, float* __restrict__ out, int out_size)
{
    extern __shared__ uint32_t smw[];
    uint32_t* Wsm = smw;                 // [192][BW1] bf16 W2^T
    uint32_t* Asm = smw + N2 * BW1;      // [128][AW] bf16 h1 chunk
    float* b2s = (float*)(Asm + 128 * AW);
    float* w3s = b2s + N2;
    float* a_s = w3s + N2;
    float* u_s = a_s + DIMN;
    float* v_s = u_s + DIMN;
    float* dns = v_s + DIMN;
    float* sps = dns + 128;
    float* zbuf = sps + 128;
    const int tid = threadIdx.x, lane = tid & 31, wid = tid >> 5;
    const int wm = wid & 3, wn = wid >> 2;   // 4 x 4 warp grid, tile 32m x 48n

    // ldmatrix lane-address bases (bytes)
    const uint32_t wsm_b = smem_u32(Wsm);
    const uint32_t asm_b = smem_u32(Asm);
    // A x4: m0 rows 0-7, m1 rows 8-15, m2 rows 0-7 col+4w, m3 rows 8-15 col+4w
    const uint32_t a_off =
        ((uint32_t)((wm * 32 + (lane & 7) + (lane & 8)) * AW + ((lane & 16) ? 4 : 0))) * 4u;
    // B x4: m0 n0-7 k0-3, m1 n0-7 k4-7, m2 n8-15 k0-3, m3 n8-15 k4-7
    const uint32_t b_off =
        ((uint32_t)((wn * 48 + (lane & 7) + ((lane & 16) >> 1)) * BW1 + ((lane & 8) ? 4 : 0))) * 4u;

    for (int i = tid; i < N2 * 48; i += 512) {       // W2^T via uint4
        int n = i / 48, w4 = i - n * 48;
        *(uint4*)&Wsm[n * BW1 + w4 * 4] = ((const uint4*)g_W2T)[(size_t)n * 48 + w4];
    }
    for (int i = tid; i < N2; i += 512) { b2s[i] = b2[i]; w3s[i] = W3[i]; }
    for (int i = tid; i < DIMN; i += 512) {
        u_s[i] = W1[768 * DIMN + i];
        v_s[i] = W1[769 * DIMN + i];
    }

    for (int u = blockIdx.x; u < QN * 32; u += gridDim.x) {
        int q = u >> 5, dt = u & 31, d0 = dt << 7;
        __syncthreads();                               // prev unit done with smem
        for (int i = tid; i < DIMN; i += 512) a_s[i] = g_A32[q * DIMN + i];
        if (tid < 128) {
            dns[tid] = g_dense[q * DN + d0 + tid];
            sps[tid] = sparse[q * DN + d0 + tid];
            zbuf[tid] = 0.f;
        }
        float acc[2][6][4];
#pragma unroll
        for (int a = 0; a < 2; a++)
#pragma unroll
            for (int b = 0; b < 6; b++)
#pragma unroll
                for (int c = 0; c < 4; c++) acc[a][b][c] = 0.f;

        for (int ch = 0; ch < 2; ch++) {
            __syncthreads();   // a_s visible (ch0) / prev mma done with Asm (ch1)
#pragma unroll 2
            for (int rr = 0; rr < 8; rr++) {
                int r = wid * 8 + rr;
                float dsc = dns[r], ssc = sps[r];
                const uint32_t* bdrow = (const uint32_t*)g_Bd + (size_t)(d0 + r) * 192 + ch * 96;
#pragma unroll
                for (int cc = 0; cc < 3; cc++) {
                    int c = lane + 32 * cc;
                    int k = ch * 192 + 2 * c;
                    uint32_t bdw = bdrow[c];
                    float2 bv = __bfloat1622float2(*(__nv_bfloat162*)&bdw);
                    float2 av = *(const float2*)&a_s[k];
                    float2 uv = *(const float2*)&u_s[k];
                    float2 vv = *(const float2*)&v_s[k];
                    float x0 = av.x + bv.x + dsc * uv.x + ssc * vv.x;
                    float x1 = av.y + bv.y + dsc * uv.y + ssc * vv.y;
                    Asm[r * AW + c] = packbf(fmaxf(x0, 0.f), fmaxf(x1, 0.f));
                }
            }
            __syncthreads();
            uint32_t bbase = wsm_b + b_off + (uint32_t)(ch * 96) * 4u;
#pragma unroll
            for (int ks = 0; ks < 12; ks++) {
                uint32_t a[2][4], bfr[3][4];
#pragma unroll
                for (int im = 0; im < 2; im++)
                    ldsm4(a[im], asm_b + a_off + (uint32_t)(im * 16 * AW * 4 + ks * 32));
#pragma unroll
                for (int p = 0; p < 3; p++)
                    ldsm4(bfr[p], bbase + (uint32_t)(p * 16 * BW1 * 4 + ks * 32));
#pragma unroll
                for (int im = 0; im < 2; im++)
#pragma unroll
                    for (int p = 0; p < 3; p++) {
                        mma16816(acc[im][2 * p],     a[im], &bfr[p][0]);
                        mma16816(acc[im][2 * p + 1], a[im], &bfr[p][2]);
                    }
            }
        }
        // epilogue: z[m] = sum_n relu(D + b2) * W3
#pragma unroll
        for (int im = 0; im < 2; im++)
#pragma unroll
            for (int hf = 0; hf < 2; hf++) {
                int m = wm * 32 + im * 16 + hf * 8 + (lane >> 2);
                float val = 0.f;
#pragma unroll
                for (int jn = 0; jn < 6; jn++) {
                    int n = wn * 48 + jn * 8 + (lane & 3) * 2;
                    val += fmaxf(acc[im][jn][hf * 2]     + b2s[n],     0.f) * w3s[n];
                    val += fmaxf(acc[im][jn][hf * 2 + 1] + b2s[n + 1], 0.f) * w3s[n + 1];
                }
                val += __shfl_xor_sync(0xffffffffu, val, 1);
                val += __shfl_xor_sync(0xffffffffu, val, 2);
                if ((lane & 3) == 0) atomicAdd(&zbuf[m], val);
            }
        __syncthreads();
        if (tid < 128) {
            float z = zbuf[tid] + b3[0];
            float w = 1.f / (1.f + expf(-z));
            float dn = dns[tid], sp = sps[tid];
            float fin = w * dn + (1.f - w) * sp;
            int o = q * DN + d0 + tid;
            if (o < out_size)          out[o] = fin;
            if (QD + o < out_size)     out[QD + o] = dn;
            if (2 * QD + o < out_size) out[2 * QD + o] = sp;
        }
    }
}

extern "C" void kernel_launch(void* const* d_in, const int* in_sizes, int n_in,
                              void* d_out, int out_size)
{
    const float* qd     = (const float*)d_in[0];
    const float* doc    = (const float*)d_in[1];
    const float* sparse = (const float*)d_in[2];
    const float* W1     = (const float*)d_in[3];
    const float* b1     = (const float*)d_in[4];
    const float* W2     = (const float*)d_in[5];
    const float* b2     = (const float*)d_in[6];
    const float* W3     = (const float*)d_in[7];
    const float* b3     = (const float*)d_in[8];
    float* out = (float*)d_out;

    const int SMEM_K1 = (96 * BW1 + 64 * AW) * 4;                 // 100864
    const int SMEM_K2 = (N2 * BW1 + 128 * AW) * 4 + 1920 * 4;     // 209408
    cudaFuncSetAttribute(hr_k1f, cudaFuncAttributeMaxDynamicSharedMemorySize, SMEM_K1);
    cudaFuncSetAttribute(hr_k2, cudaFuncAttributeMaxDynamicSharedMemorySize, SMEM_K2);

    hr_prep_t<<<TBLK_W2 + TBLK_W1, 256>>>(W1, W2);
    hr_k1f<<<K1BLK + ABLK + DBLK, 256, SMEM_K1>>>(doc, qd, W1, b1);
    hr_k2<<<148, 512, SMEM_K2>>>(sparse, W1, b2, W3, b3, out, out_size);
}